// round 2
// baseline (speedup 1.0000x reference)
#include <cuda_runtime.h>
#include <cstdint>

// ---------------- problem constants -------------------------------------
#define B_    4
#define S_    8192
#define D_    2048
#define HD_   128
#define NTOK  (B_ * S_)            // 32768 tokens
#define NCOL  512                  // 4 projections * HD
#define NBLK  (B_ * (S_ / 4))      // 8192 output blocks
#define OUT_ELEMS (NBLK * HD_)     // 1048576

// GEMM tiling
#define BM 128
#define BN 256
#define BK 32
#define NKC (D_ / BK)              // 64 k-chunks

// ---------------- scratch (static device globals) ------------------------
__device__ float g_Wt[NCOL * D_];                 // 4 MB, K-major tf32-rounded weights
__device__ float g_C[(size_t)NTOK * NCOL];        // 64 MB, GEMM output

// ---------------- helpers ------------------------------------------------
__device__ __forceinline__ uint32_t smem_to_u32(const void* p) {
    uint32_t a;
    asm("{ .reg .u64 t; cvta.to.shared.u64 t, %1; cvt.u32.u64 %0, t; }"
        : "=r"(a) : "l"(p));
    return a;
}

__device__ __forceinline__ float tf32r(float x) {
    uint32_t u;
    asm("cvt.rna.tf32.f32 %0, %1;" : "=r"(u) : "f"(x));
    return __uint_as_float(u);
}

#define CP_ASYNC16(dst_u32, src_ptr) \
    asm volatile("cp.async.cg.shared.global [%0], [%1], 16;" \
                 :: "r"(dst_u32), "l"(src_ptr) : "memory")
#define CP_ASYNC_COMMIT() asm volatile("cp.async.commit_group;" ::: "memory")
#define CP_ASYNC_WAIT0()  asm volatile("cp.async.wait_group 0;" ::: "memory")

#define MMA_TF32(d, a, b) \
    asm volatile("mma.sync.aligned.m16n8k8.row.col.f32.tf32.tf32.f32 " \
                 "{%0,%1,%2,%3}, {%4,%5,%6,%7}, {%8,%9}, {%0,%1,%2,%3};" \
                 : "+f"((d)[0]), "+f"((d)[1]), "+f"((d)[2]), "+f"((d)[3]) \
                 : "r"((a)[0]), "r"((a)[1]), "r"((a)[2]), "r"((a)[3]), \
                   "r"((b)[0]), "r"((b)[1]))

// smem float-index layout: A stage 4096 floats, B stage 8192 floats
#define SA_OFF(buf) ((buf) * 4096)
#define SB_OFF(buf) (8192 + (buf) * 8192)
#define SMEM_FLOATS (8192 + 16384)            // 24576 floats = 96 KB

// XOR-16B swizzled offset inside a tile: row stride 32 floats (128B)
__device__ __forceinline__ int sw_off(int row, int c4) {
    return row * 32 + ((c4 ^ (row & 7)) << 2);
}

// ---------------- kernel 1: weight transpose + tf32 rounding -------------
__global__ void prep_w_kernel(const float* __restrict__ wka,
                              const float* __restrict__ wkb,
                              const float* __restrict__ wza,
                              const float* __restrict__ wzb)
{
    int k = blockIdx.x * blockDim.x + threadIdx.x;   // 0..2047
    int n = blockIdx.y;                              // 0..511
    const float* w = (n < 128) ? wka : (n < 256) ? wkb : (n < 384) ? wza : wzb;
    int j = n & 127;
    g_Wt[(size_t)n * D_ + k] = tf32r(w[(size_t)k * HD_ + j]);
}

// ---------------- kernel 2: pipelined mma.sync tf32 GEMM -----------------
// C[t, 0:512] = h[t, :] @ [Wkva | Wkvb | Wza | Wzb]
__global__ void __launch_bounds__(512, 1)
gemm_kernel(const float* __restrict__ h)
{
    extern __shared__ float sm[];
    const uint32_t smem_base = smem_to_u32(sm);

    const int tid    = threadIdx.x;
    const int lane   = tid & 31;
    const int wid    = tid >> 5;
    const int warp_m = wid >> 3;          // 0..1  (64 rows each)
    const int warp_n = wid & 7;           // 0..7  (32 cols each)

    const int t0 = (int)(blockIdx.x >> 1) * BM;
    const int n0 = (int)(blockIdx.x & 1) * BN;

    // per-thread tile-load coordinates
    const int a_row0 = tid >> 3;          // e = tid      -> rows 0..63
    const int a_row1 = (tid + 512) >> 3;  //              -> rows 64..127
    const int a_c4   = tid & 7;

    float4 aR[2];

    // -------- prologue: stage 0 --------
    {
        aR[0] = *(const float4*)(h + (size_t)(t0 + a_row0) * D_ + a_c4 * 4);
        aR[1] = *(const float4*)(h + (size_t)(t0 + a_row1) * D_ + a_c4 * 4);
        #pragma unroll
        for (int j = 0; j < 4; ++j) {
            int e = tid + j * 512;
            int row = e >> 3, c4 = e & 7;
            uint32_t dst = smem_base + (uint32_t)(SB_OFF(0) + sw_off(row, c4)) * 4u;
            CP_ASYNC16(dst, g_Wt + (size_t)(n0 + row) * D_ + c4 * 4);
        }
        CP_ASYNC_COMMIT();
        float4 v0 = aR[0], v1 = aR[1];
        v0.x = tf32r(v0.x); v0.y = tf32r(v0.y); v0.z = tf32r(v0.z); v0.w = tf32r(v0.w);
        v1.x = tf32r(v1.x); v1.y = tf32r(v1.y); v1.z = tf32r(v1.z); v1.w = tf32r(v1.w);
        *(float4*)(sm + SA_OFF(0) + sw_off(a_row0, a_c4)) = v0;
        *(float4*)(sm + SA_OFF(0) + sw_off(a_row1, a_c4)) = v1;
        CP_ASYNC_WAIT0();
        __syncthreads();
    }

    float acc[4][4][4];
    #pragma unroll
    for (int mt = 0; mt < 4; ++mt)
        #pragma unroll
        for (int nt = 0; nt < 4; ++nt)
            #pragma unroll
            for (int i = 0; i < 4; ++i) acc[mt][nt][i] = 0.0f;

    const uint32_t* smu = (const uint32_t*)sm;

    for (int c = 0; c < NKC; ++c) {
        const int buf = c & 1;

        if (c + 1 < NKC) {
            const int k1 = (c + 1) * BK;
            aR[0] = *(const float4*)(h + (size_t)(t0 + a_row0) * D_ + k1 + a_c4 * 4);
            aR[1] = *(const float4*)(h + (size_t)(t0 + a_row1) * D_ + k1 + a_c4 * 4);
            #pragma unroll
            for (int j = 0; j < 4; ++j) {
                int e = tid + j * 512;
                int row = e >> 3, c4 = e & 7;
                uint32_t dst = smem_base + (uint32_t)(SB_OFF(buf ^ 1) + sw_off(row, c4)) * 4u;
                CP_ASYNC16(dst, g_Wt + (size_t)(n0 + row) * D_ + k1 + c4 * 4);
            }
            CP_ASYNC_COMMIT();
        }

        // -------- compute on buf --------
        #pragma unroll
        for (int ks = 0; ks < 4; ++ks) {
            uint32_t af[4][4], bf[4][2];
            #pragma unroll
            for (int mt = 0; mt < 4; ++mt) {
                int r  = warp_m * 64 + mt * 16 + (lane >> 2);
                int cc = lane & 3;
                int s0 = (ks * 2)     ^ (r & 7);
                int s1 = (ks * 2 + 1) ^ (r & 7);
                af[mt][0] = smu[SA_OFF(buf) + r * 32 + (s0 << 2) + cc];
                af[mt][1] = smu[SA_OFF(buf) + (r + 8) * 32 + (s0 << 2) + cc];
                af[mt][2] = smu[SA_OFF(buf) + r * 32 + (s1 << 2) + cc];
                af[mt][3] = smu[SA_OFF(buf) + (r + 8) * 32 + (s1 << 2) + cc];
            }
            #pragma unroll
            for (int nt = 0; nt < 4; ++nt) {
                int n  = warp_n * 32 + nt * 8 + (lane >> 2);
                int cc = lane & 3;
                int s0 = (ks * 2)     ^ (n & 7);
                int s1 = (ks * 2 + 1) ^ (n & 7);
                bf[nt][0] = smu[SB_OFF(buf) + n * 32 + (s0 << 2) + cc];
                bf[nt][1] = smu[SB_OFF(buf) + n * 32 + (s1 << 2) + cc];
            }
            #pragma unroll
            for (int mt = 0; mt < 4; ++mt)
                #pragma unroll
                for (int nt = 0; nt < 4; ++nt)
                    MMA_TF32(acc[mt][nt], af[mt], bf[nt]);
        }

        if (c + 1 < NKC) {
            float4 v0 = aR[0], v1 = aR[1];
            v0.x = tf32r(v0.x); v0.y = tf32r(v0.y); v0.z = tf32r(v0.z); v0.w = tf32r(v0.w);
            v1.x = tf32r(v1.x); v1.y = tf32r(v1.y); v1.z = tf32r(v1.z); v1.w = tf32r(v1.w);
            *(float4*)(sm + SA_OFF(buf ^ 1) + sw_off(a_row0, a_c4)) = v0;
            *(float4*)(sm + SA_OFF(buf ^ 1) + sw_off(a_row1, a_c4)) = v1;
            CP_ASYNC_WAIT0();
        }
        __syncthreads();
    }

    // -------- writeback --------
    #pragma unroll
    for (int mt = 0; mt < 4; ++mt) {
        int r0 = t0 + warp_m * 64 + mt * 16 + (lane >> 2);
        #pragma unroll
        for (int nt = 0; nt < 4; ++nt) {
            int cb = n0 + warp_n * 32 + nt * 8 + (lane & 3) * 2;
            *(float2*)(g_C + (size_t)r0 * NCOL + cb) =
                make_float2(acc[mt][nt][0], acc[mt][nt][1]);
            *(float2*)(g_C + (size_t)(r0 + 8) * NCOL + cb) =
                make_float2(acc[mt][nt][2], acc[mt][nt][3]);
        }
    }
}

// ---------------- kernel 3: masked softmax compression -------------------
// C columns: [0,128)=c_a, [128,256)=c_b, [256,384)=z_a, [384,512)=z_b
__global__ void epilogue_kernel(const float* __restrict__ b_a,
                                const float* __restrict__ b_b,
                                float* __restrict__ out, int dup)
{
    int g  = blockIdx.x * blockDim.x + threadIdx.x;   // 0..1048575
    int d  = g & 127;
    int bi = g >> 7;           // global block id 0..8191
    int i  = bi & 2047;        // block within batch
    int b  = bi >> 11;         // batch
    int t0 = b * S_ + i * 4;   // first token of current block

    float logit[8], val[8];
    const bool has_prev = (i > 0);
    #pragma unroll
    for (int j = 0; j < 4; ++j) {
        if (has_prev) {
            const float* Cp = g_C + (size_t)(t0 - 4 + j) * NCOL;
            logit[j] = Cp[384 + d] + b_b[j * 128 + d];
            val[j]   = Cp[128 + d];
        } else {
            logit[j] = -3.0e38f;
            val[j]   = 0.0f;
        }
        const float* Cc = g_C + (size_t)(t0 + j) * NCOL;
        logit[4 + j] = Cc[256 + d] + b_a[j * 128 + d];
        val[4 + j]   = Cc[d];
    }
    float mx = logit[0];
    #pragma unroll
    for (int j = 1; j < 8; ++j) mx = fmaxf(mx, logit[j]);
    float s = 0.0f, acc = 0.0f;
    #pragma unroll
    for (int j = 0; j < 8; ++j) {
        float e = __expf(logit[j] - mx);
        s   += e;
        acc += e * val[j];
    }
    float r = acc / s;
    out[g] = r;
    if (dup) out[g + OUT_ELEMS] = r;
}

// ---------------- launch ------------------------------------------------
extern "C" void kernel_launch(void* const* d_in, const int* in_sizes, int n_in,
                              void* d_out, int out_size)
{
    const float* h   = (const float*)d_in[0];
    const float* wka = (const float*)d_in[1];
    const float* wkb = (const float*)d_in[2];
    const float* wza = (const float*)d_in[3];
    const float* wzb = (const float*)d_in[4];
    const float* ba  = (const float*)d_in[5];
    const float* bb  = (const float*)d_in[6];
    float* out = (float*)d_out;

    cudaFuncSetAttribute(gemm_kernel,
                         cudaFuncAttributeMaxDynamicSharedMemorySize,
                         SMEM_FLOATS * (int)sizeof(float));

    prep_w_kernel<<<dim3(D_ / 256, NCOL), 256>>>(wka, wkb, wza, wzb);
    gemm_kernel<<<(NTOK / BM) * (NCOL / BN), 512, SMEM_FLOATS * sizeof(float)>>>(h);

    int dup = (out_size >= 2 * OUT_ELEMS) ? 1 : 0;
    epilogue_kernel<<<OUT_ELEMS / 256, 256>>>(ba, bb, out, dup);
}